// round 7
// baseline (speedup 1.0000x reference)
#include <cuda_runtime.h>
#include <cuda_bf16.h>
#include <math.h>

// ---------------- problem constants ----------------
#define BB 2          // batch
#define CC 256        // channels
#define DI 512
#define NST 16        // state dim N
#define RR 16         // dt rank
#define LTOT 4096     // full sequence length
#define TOK 2048      // base tokens per batch (1024 from x0 + 1024 from x1)
// x0: (B,256,128,128) -> down (32,32); x1: (B,256,256,64) -> down (64,16)

// ---------------- scratch (device globals; no allocation APIs) ----------------
__device__ float g_patches[4096u * 4096u];       // im2col of down-conv        64 MB
__device__ float g_dg[4096u * 256u];             // down-gemm output            4 MB
__device__ float g_xf[2][4096u * 256u];          // LN'd base tokens fwd/rev    8 MB
__device__ float g_xz[2][4096u * 1024u];         // in-proj out (half length)  32 MB
__device__ float g_xc[2][8192u * 512u];          // conv+silu (full length)    32 MB
__device__ float g_xdb[2][8192u * 48u];          // xp projection               3 MB
__device__ float g_dtb[2][8192u * 512u];         // softplus dt                32 MB
__device__ float g_y[2][8192u * 512u];           // scan out / gated           32 MB
__device__ float g_yp[2][8192u * 256u];          // out-proj                   16 MB
__device__ float g_grid0[2u * 256u * 32u * 32u]; // pre-upsample grid 0         2 MB
__device__ float g_grid1[2u * 256u * 64u * 16u]; // pre-upsample grid 1         2 MB

// ---------------- im2col for down conv ----------------
// patches[row][k], row = b*2048 + tok, k = c*16 + dy*4 + dx
__global__ void im2col_kernel(const float* __restrict__ x0, const float* __restrict__ x1) {
    int row = blockIdx.x;            // 0..4095
    int b = row >> 11;
    int tl = row & 2047;
    for (int k = threadIdx.x; k < 4096; k += 256) {
        int c = k >> 4;
        int dy = (k >> 2) & 3;
        int dx = k & 3;
        float v;
        if (tl < 1024) {             // x0 tokens, (32x32), H=W=128
            int oh = tl >> 5, ow = tl & 31;
            v = x0[(((size_t)(b * 256 + c) * 128) + (oh * 4 + dy)) * 128 + ow * 4 + dx];
        } else {                     // x1 tokens, (64x16), H=256, W=64
            int t2 = tl - 1024;
            int oh = t2 >> 4, ow = t2 & 15;
            v = x1[(((size_t)(b * 256 + c) * 256) + (oh * 4 + dy)) * 64 + ow * 4 + dx];
        }
        g_patches[(size_t)row * 4096 + k] = v;
    }
}

// ---------------- generic register-tiled SGEMM: C = A[M,K] @ W[N,K]^T ----------------
// mode 0: none; 1: +bias[n]; 2: softplus(v + bias[n])
#define BM 64
#define BN 64
#define BKT 16
__global__ void __launch_bounds__(256) gemm_kernel(
    const float* __restrict__ A, int lda,
    const float* __restrict__ W,
    const float* __restrict__ bias,
    float* __restrict__ Cm, int ldc,
    int M, int N, int K, int mode)
{
    __shared__ float As[BKT][BM + 1];
    __shared__ float Bs[BKT][BN + 1];
    int tid = threadIdx.x;
    int tx = tid & 15, ty = tid >> 4;
    int m0 = blockIdx.y * BM;
    int n0 = blockIdx.x * BN;
    float acc[4][4] = {};
    for (int k0 = 0; k0 < K; k0 += BKT) {
#pragma unroll
        for (int i = 0; i < 4; i++) {
            int flat = tid + 256 * i;                 // 0..1023
            int k = flat & 15, m = flat >> 4;
            int gm = m0 + m, gk = k0 + k;
            As[k][m] = (gm < M && gk < K) ? A[(size_t)gm * lda + gk] : 0.f;
        }
#pragma unroll
        for (int i = 0; i < 4; i++) {
            int flat = tid + 256 * i;
            int k = flat & 15, n = flat >> 4;
            int gn = n0 + n, gk = k0 + k;
            Bs[k][n] = (gn < N && gk < K) ? W[(size_t)gn * K + gk] : 0.f;
        }
        __syncthreads();
#pragma unroll
        for (int k = 0; k < BKT; k++) {
            float a[4], bvl[4];
#pragma unroll
            for (int i = 0; i < 4; i++) a[i] = As[k][ty + 16 * i];
#pragma unroll
            for (int j = 0; j < 4; j++) bvl[j] = Bs[k][tx + 16 * j];
#pragma unroll
            for (int i = 0; i < 4; i++)
#pragma unroll
                for (int j = 0; j < 4; j++)
                    acc[i][j] = fmaf(a[i], bvl[j], acc[i][j]);
        }
        __syncthreads();
    }
#pragma unroll
    for (int i = 0; i < 4; i++) {
        int gm = m0 + ty + 16 * i;
        if (gm >= M) continue;
#pragma unroll
        for (int j = 0; j < 4; j++) {
            int gn = n0 + tx + 16 * j;
            if (gn >= N) continue;
            float v = acc[i][j];
            if (mode >= 1) v += bias[gn];
            if (mode == 2) v = (v > 20.f) ? v : log1pf(expf(v));
            Cm[(size_t)gm * ldc + gn] = v;
        }
    }
}

// ---------------- LayerNorm over channels; writes fwd + per-batch-reversed copies ----------------
__global__ void ln_kernel(const float* __restrict__ ln_w, const float* __restrict__ ln_b) {
    int row = blockIdx.x;      // 0..4095 (b*2048 + tt)
    int c = threadIdx.x;       // 0..255
    __shared__ float red[8];
    float v = g_dg[(size_t)row * 256 + c];
    float s = v;
#pragma unroll
    for (int o = 16; o; o >>= 1) s += __shfl_xor_sync(0xffffffffu, s, o);
    if ((c & 31) == 0) red[c >> 5] = s;
    __syncthreads();
    float mean = 0.f;
#pragma unroll
    for (int i = 0; i < 8; i++) mean += red[i];
    mean *= (1.0f / 256.0f);
    __syncthreads();
    float dv = v - mean;
    float s2 = dv * dv;
#pragma unroll
    for (int o = 16; o; o >>= 1) s2 += __shfl_xor_sync(0xffffffffu, s2, o);
    if ((c & 31) == 0) red[c >> 5] = s2;
    __syncthreads();
    float var = 0.f;
#pragma unroll
    for (int i = 0; i < 8; i++) var += red[i];
    var *= (1.0f / 256.0f);
    float outv = dv * rsqrtf(var + 1e-6f) * ln_w[c] + ln_b[c];
    int b = row >> 11, tt = row & 2047;
    g_xf[0][(size_t)row * 256 + c] = outv;
    g_xf[1][(size_t)((b << 11) + (2047 - tt)) * 256 + c] = outv;
}

// ---------------- causal depthwise conv (K=4) + silu ----------------
__global__ void dwconv_kernel(const float* __restrict__ c1_w, const float* __restrict__ c1_b) {
    int idx = blockIdx.x * blockDim.x + threadIdx.x;   // 2*2*4096*512 = 8388608
    int d = idx & 511;
    int t = (idx >> 9) & 4095;
    int b = (idx >> 21) & 1;
    int dir = idx >> 22;
    const float* xz = g_xz[dir];
    const float* w = c1_w + (size_t)(dir * 512 + d) * 4;
    float acc = c1_b[dir * 512 + d];
#pragma unroll
    for (int k = 0; k < 4; k++) {
        int s = t - 3 + k;
        if (s >= 0)
            acc = fmaf(w[k], xz[(size_t)((b << 11) + (s & 2047)) * 1024 + d], acc);
    }
    float sv = acc / (1.0f + __expf(-acc));   // silu
    g_xc[dir][(size_t)(b * 4096 + t) * 512 + d] = sv;
}

// ---------------- selective scan ----------------
// block = 512 threads = 32 d-channels x 16 states; one thread per (d,n)
__global__ void __launch_bounds__(512) scan_kernel(const float* __restrict__ a_log,
                                                   const float* __restrict__ d_p) {
    int dir = blockIdx.z, b = blockIdx.y, dg = blockIdx.x;
    int tid = threadIdx.x;
    int dloc = tid >> 4, n = tid & 15;
    int d = dg * 32 + dloc;
    float acoef = -__expf(a_log[(size_t)(dir * 512 + d) * 16 + n]);
    float dp = d_p[dir * 512 + d];
    float h = 0.f;
    const float* dtp = g_dtb[dir] + (size_t)b * 4096 * 512;
    const float* xcp = g_xc[dir]  + (size_t)b * 4096 * 512;
    const float* xdbp = g_xdb[dir] + (size_t)b * 4096 * 48;
    float* yp = g_y[dir] + (size_t)b * 4096 * 512;
    for (int t = 0; t < 4096; t++) {
        float dtv = dtp[(size_t)t * 512 + d];
        float uv  = xcp[(size_t)t * 512 + d];
        float bn  = xdbp[(size_t)t * 48 + 16 + n];
        float cn  = xdbp[(size_t)t * 48 + 32 + n];
        float a = __expf(dtv * acoef);
        h = fmaf(a, h, dtv * uv * bn);
        float p = h * cn;
        p += __shfl_xor_sync(0xffffffffu, p, 1);
        p += __shfl_xor_sync(0xffffffffu, p, 2);
        p += __shfl_xor_sync(0xffffffffu, p, 4);
        p += __shfl_xor_sync(0xffffffffu, p, 8);
        if (n == 0) yp[(size_t)t * 512 + d] = fmaf(uv, dp, p);
    }
}

// ---------------- gate: y *= silu(z) ----------------
__global__ void gate_kernel() {
    int idx = blockIdx.x * blockDim.x + threadIdx.x;   // 8388608
    int d = idx & 511;
    int t = (idx >> 9) & 4095;
    int b = (idx >> 21) & 1;
    int dir = idx >> 22;
    float z = g_xz[dir][(size_t)((b << 11) + (t & 2047)) * 1024 + 512 + d];
    float sz = z / (1.0f + __expf(-z));
    g_y[dir][(size_t)(b * 4096 + t) * 512 + d] *= sz;
}

// ---------------- combine fwd/bwd + scatter into spatial grids ----------------
__device__ __forceinline__ float comb_val(int b, int t, int c) {
    return 0.5f * (g_yp[0][(size_t)(b * 4096 + t) * 256 + c] +
                   g_yp[1][(size_t)(b * 4096 + 4095 - t) * 256 + c]);
}
__global__ void scatter0_kernel() {
    int idx = blockIdx.x * blockDim.x + threadIdx.x;   // 2*256*32*32 = 524288
    int w = idx & 31;
    int h = (idx >> 5) & 31;
    int c = (idx >> 10) & 255;
    int b = idx >> 18;
    int t1 = h * 32 + w;               // hw chunk (chunk 0)
    int t2 = 2048 + w * 32 + h;        // wh chunk (chunk 2), transposed scatter
    g_grid0[idx] = comb_val(b, t1, c) + comb_val(b, t2, c);
}
__global__ void scatter1_kernel() {
    int idx = blockIdx.x * blockDim.x + threadIdx.x;   // 2*256*64*16 = 524288
    int w = idx & 15;
    int h = (idx >> 4) & 63;
    int c = (idx >> 10) & 255;
    int b = idx >> 18;
    int t1 = 1024 + h * 16 + w;        // hw chunk (chunk 1)
    int t2 = 3072 + w * 64 + h;        // wh chunk (chunk 3)
    g_grid1[idx] = comb_val(b, t1, c) + comb_val(b, t2, c);
}

// ---------------- x4 bilinear upsample (jax half-pixel; edge renorm == clamp for 2 taps) ----------------
__device__ __forceinline__ void up_coords(int o, int nmax, int& i0, int& i1, float& f) {
    const float F[4] = {0.625f, 0.875f, 0.125f, 0.375f};
    int r = o & 3, p = o >> 2;
    f = F[r];
    i0 = p - (r < 2 ? 1 : 0);
    i1 = i0 + 1;
    if (i0 < 0) i0 = 0;
    if (i1 > nmax) i1 = nmax;
}
__global__ void up0_kernel(float* __restrict__ out) {
    int idx = blockIdx.x * blockDim.x + threadIdx.x;   // 2*256*128*128 = 8388608
    int j = idx & 127;
    int i = (idx >> 7) & 127;
    int c = (idx >> 14) & 255;
    int b = idx >> 22;
    int i0, i1, j0, j1; float fi, fj;
    up_coords(i, 31, i0, i1, fi);
    up_coords(j, 31, j0, j1, fj);
    const float* g = g_grid0 + (size_t)(b * 256 + c) * 1024;
    float v00 = g[i0 * 32 + j0], v01 = g[i0 * 32 + j1];
    float v10 = g[i1 * 32 + j0], v11 = g[i1 * 32 + j1];
    out[idx] = (1.f - fi) * ((1.f - fj) * v00 + fj * v01) + fi * ((1.f - fj) * v10 + fj * v11);
}
__global__ void up1_kernel(float* __restrict__ out) {
    int idx = blockIdx.x * blockDim.x + threadIdx.x;   // 2*256*256*64 = 8388608
    int j = idx & 63;
    int i = (idx >> 6) & 255;
    int c = (idx >> 14) & 255;
    int b = idx >> 22;
    int i0, i1, j0, j1; float fi, fj;
    up_coords(i, 63, i0, i1, fi);
    up_coords(j, 15, j0, j1, fj);
    const float* g = g_grid1 + (size_t)(b * 256 + c) * 1024;
    float v00 = g[i0 * 16 + j0], v01 = g[i0 * 16 + j1];
    float v10 = g[i1 * 16 + j0], v11 = g[i1 * 16 + j1];
    out[idx] = (1.f - fi) * ((1.f - fj) * v00 + fj * v01) + fi * ((1.f - fj) * v10 + fj * v11);
}

// ---------------- host launch ----------------
extern "C" void kernel_launch(void* const* d_in, const int* in_sizes, int n_in,
                              void* d_out, int out_size) {
    const float* x0     = (const float*)d_in[0];
    const float* x1     = (const float*)d_in[1];
    const float* conv_w = (const float*)d_in[2];
    const float* conv_b = (const float*)d_in[3];
    const float* ln_w   = (const float*)d_in[4];
    const float* ln_b   = (const float*)d_in[5];
    const float* in_w   = (const float*)d_in[6];
    const float* c1_w   = (const float*)d_in[7];
    const float* c1_b   = (const float*)d_in[8];
    const float* xp_w   = (const float*)d_in[9];
    const float* dt_w   = (const float*)d_in[10];
    const float* dt_b   = (const float*)d_in[11];
    const float* a_log  = (const float*)d_in[12];
    const float* d_p    = (const float*)d_in[13];
    const float* out_w  = (const float*)d_in[14];
    float* out = (float*)d_out;

    float *patches, *dg, *xf, *xz, *xc, *xdb, *dtb, *yb, *ypb;
    cudaGetSymbolAddress((void**)&patches, g_patches);
    cudaGetSymbolAddress((void**)&dg, g_dg);
    cudaGetSymbolAddress((void**)&xf, g_xf);
    cudaGetSymbolAddress((void**)&xz, g_xz);
    cudaGetSymbolAddress((void**)&xc, g_xc);
    cudaGetSymbolAddress((void**)&xdb, g_xdb);
    cudaGetSymbolAddress((void**)&dtb, g_dtb);
    cudaGetSymbolAddress((void**)&yb, g_y);
    cudaGetSymbolAddress((void**)&ypb, g_yp);

    // 1) im2col + down-conv GEMM (+bias)
    im2col_kernel<<<4096, 256>>>(x0, x1);
    gemm_kernel<<<dim3(256 / BN, 4096 / BM), 256>>>(patches, 4096, conv_w, conv_b,
                                                    dg, 256, 4096, 256, 4096, 1);
    // 2) LayerNorm -> base tokens fwd/rev
    ln_kernel<<<4096, 256>>>(ln_w, ln_b);

    // 3) in-proj per direction (half-length: sequence repeats the base tokens)
    for (int dir = 0; dir < 2; dir++) {
        gemm_kernel<<<dim3(1024 / BN, 4096 / BM), 256>>>(
            xf + (size_t)dir * 4096 * 256, 256,
            in_w + (size_t)dir * 1024 * 256, nullptr,
            xz + (size_t)dir * 4096 * 1024, 1024, 4096, 1024, 256, 0);
    }

    // 4) causal dwconv + silu (full length, both dirs)
    dwconv_kernel<<<32768, 256>>>(c1_w, c1_b);

    // 5) xp projection and dt (softplus + bias) per direction
    for (int dir = 0; dir < 2; dir++) {
        gemm_kernel<<<dim3(1, 8192 / BM), 256>>>(
            xc + (size_t)dir * 8192 * 512, 512,
            xp_w + (size_t)dir * 48 * 512, nullptr,
            xdb + (size_t)dir * 8192 * 48, 48, 8192, 48, 512, 0);
        gemm_kernel<<<dim3(512 / BN, 8192 / BM), 256>>>(
            xdb + (size_t)dir * 8192 * 48, 48,
            dt_w + (size_t)dir * 512 * 16, dt_b + (size_t)dir * 512,
            dtb + (size_t)dir * 8192 * 512, 512, 8192, 512, 16, 2);
    }

    // 6) selective scan (both dirs, both batches)
    scan_kernel<<<dim3(16, BB, 2), 512>>>(a_log, d_p);

    // 7) gate + out-proj
    gate_kernel<<<32768, 256>>>();
    for (int dir = 0; dir < 2; dir++) {
        gemm_kernel<<<dim3(256 / BN, 8192 / BM), 256>>>(
            yb + (size_t)dir * 8192 * 512, 512,
            out_w + (size_t)dir * 256 * 512, nullptr,
            ypb + (size_t)dir * 8192 * 256, 256, 8192, 256, 512, 0);
    }

    // 8) combine directions + scatter to grids, then bilinear x4 upsample
    scatter0_kernel<<<2048, 256>>>();
    scatter1_kernel<<<2048, 256>>>();
    up0_kernel<<<32768, 256>>>(out);
    up1_kernel<<<32768, 256>>>(out + 8388608);
}

// round 10
// speedup vs baseline: 2.1678x; 2.1678x over previous
#include <cuda_runtime.h>
#include <cuda_bf16.h>
#include <math.h>

// ---------------- problem constants ----------------
#define BB 2          // batch
#define CC 256        // channels
#define DI 512
#define NST 16        // state dim N
#define LTOT 4096     // full sequence length
// x0: (B,256,128,128) -> down (32,32); x1: (B,256,256,64) -> down (64,16)
#define NCHUNK 64
#define CLEN 64       // 64 * 64 = 4096 timesteps

// ---------------- scratch (device globals; no allocation APIs) ----------------
__device__ float g_patches[4096u * 4096u];       // im2col of down-conv        64 MB
__device__ float g_dgp[4][4096u * 256u];         // split-K partials           16 MB
__device__ float g_dg[4096u * 256u];             // down-gemm output            4 MB
__device__ float g_xf[2][4096u * 256u];          // LN'd base tokens fwd/rev    8 MB
__device__ float g_xz[2][4096u * 1024u];         // in-proj out (half length)  32 MB
__device__ float g_xc[2][8192u * 512u];          // conv+silu (full length)    32 MB
__device__ float g_xdb[2][8192u * 48u];          // xp projection               3 MB
__device__ float g_dtb[2][8192u * 512u];         // softplus dt                32 MB
__device__ float g_y[2][8192u * 512u];           // scan out (gated)           32 MB
__device__ float g_yp[2][8192u * 256u];          // out-proj                   16 MB
__device__ float g_grid0[2u * 256u * 32u * 32u]; // pre-upsample grid 0         2 MB
__device__ float g_grid1[2u * 256u * 64u * 16u]; // pre-upsample grid 1         2 MB
// chunked-scan state: index z = dir*2 + b
__device__ float g_hend [4][NCHUNK][DI * NST];   //  8 MB
__device__ float g_aprod[4][NCHUNK][DI * NST];   //  8 MB
__device__ float g_hinit[4][NCHUNK][DI * NST];   //  8 MB

// ---------------- im2col for down conv ----------------
// patches[row][k], row = b*2048 + tok, k = c*16 + dy*4 + dx
__global__ void im2col_kernel(const float* __restrict__ x0, const float* __restrict__ x1) {
    int row = blockIdx.x;            // 0..4095
    int b = row >> 11;
    int tl = row & 2047;
    for (int k = threadIdx.x; k < 4096; k += 256) {
        int c = k >> 4;
        int dy = (k >> 2) & 3;
        int dx = k & 3;
        float v;
        if (tl < 1024) {             // x0 tokens, (32x32), H=W=128
            int oh = tl >> 5, ow = tl & 31;
            v = x0[(((size_t)(b * 256 + c) * 128) + (oh * 4 + dy)) * 128 + ow * 4 + dx];
        } else {                     // x1 tokens, (64x16), H=256, W=64
            int t2 = tl - 1024;
            int oh = t2 >> 4, ow = t2 & 15;
            v = x1[(((size_t)(b * 256 + c) * 256) + (oh * 4 + dy)) * 64 + ow * 4 + dx];
        }
        g_patches[(size_t)row * 4096 + k] = v;
    }
}

// ---------------- 128x128x16 SGEMM, 8x8 microtile: C = A[M,K] @ W[N,K]^T ------
// mode 0: none; 1: +bias[n]; 2: softplus(v + bias[n])
// If gridDim.z > 1 (split-K): each z-slice handles K/gridDim.z and stores RAW
// partials at Cm + z*M*ldc (mode ignored; epilogue applied by reduce kernel).
// Requires: M % 128 == 0, K % (16*gridDim.z) == 0.
__global__ void __launch_bounds__(256) gemm128_kernel(
    const float* __restrict__ A, int lda,
    const float* __restrict__ W,
    const float* __restrict__ bias,
    float* __restrict__ Cm, int ldc,
    int M, int N, int K, int mode)
{
    __shared__ float As[16][132];
    __shared__ float Bs[16][132];
    int tid = threadIdx.x;
    int tx = tid & 15, ty = tid >> 4;
    int m0 = blockIdx.y * 128;
    int n0 = blockIdx.x * 128;
    int kbeg = 0, kend = K;
    bool split = (gridDim.z > 1);
    if (split) {
        int kc = K / gridDim.z;
        kbeg = blockIdx.z * kc;
        kend = kbeg + kc;
        Cm += (size_t)blockIdx.z * M * ldc;
    }
    float acc[8][8] = {};
    for (int k0 = kbeg; k0 < kend; k0 += 16) {
#pragma unroll
        for (int i = 0; i < 8; i++) {
            int flat = tid + 256 * i;           // 0..2047
            int k = flat & 15, m = flat >> 4;   // m 0..127
            As[k][m] = A[(size_t)(m0 + m) * lda + k0 + k];
        }
#pragma unroll
        for (int i = 0; i < 8; i++) {
            int flat = tid + 256 * i;
            int k = flat & 15, n = flat >> 4;
            int gn = n0 + n;
            Bs[k][n] = (gn < N) ? W[(size_t)gn * K + k0 + k] : 0.f;
        }
        __syncthreads();
#pragma unroll
        for (int k = 0; k < 16; k++) {
            float a[8], bv[8];
            *(float4*)&a[0]  = *(const float4*)&As[k][ty * 4];
            *(float4*)&a[4]  = *(const float4*)&As[k][64 + ty * 4];
            *(float4*)&bv[0] = *(const float4*)&Bs[k][tx * 4];
            *(float4*)&bv[4] = *(const float4*)&Bs[k][64 + tx * 4];
#pragma unroll
            for (int i = 0; i < 8; i++)
#pragma unroll
                for (int j = 0; j < 8; j++)
                    acc[i][j] = fmaf(a[i], bv[j], acc[i][j]);
        }
        __syncthreads();
    }
#pragma unroll
    for (int i = 0; i < 8; i++) {
        int gm = m0 + ((i < 4) ? (ty * 4 + i) : (64 + ty * 4 + i - 4));
#pragma unroll
        for (int j = 0; j < 8; j++) {
            int gn = n0 + ((j < 4) ? (tx * 4 + j) : (64 + tx * 4 + j - 4));
            if (gn >= N) continue;
            float v = acc[i][j];
            if (!split) {
                if (mode >= 1) v += bias[gn];
                if (mode == 2) v = (v > 20.f) ? v : log1pf(expf(v));
            }
            Cm[(size_t)gm * ldc + gn] = v;
        }
    }
}

// reduce the 4 split-K partials of the down GEMM and add conv bias
__global__ void reduce_dg_kernel(const float* __restrict__ conv_b) {
    int idx = blockIdx.x * blockDim.x + threadIdx.x;   // 4096*256 = 1048576
    float s = g_dgp[0][idx] + g_dgp[1][idx] + g_dgp[2][idx] + g_dgp[3][idx];
    g_dg[idx] = s + conv_b[idx & 255];
}

// ---------------- 64x64 SGEMM (kept for the ragged N=48 xp projection) --------
#define BM 64
#define BN 64
#define BKT 16
__global__ void __launch_bounds__(256) gemm_kernel(
    const float* __restrict__ A, int lda,
    const float* __restrict__ W,
    const float* __restrict__ bias,
    float* __restrict__ Cm, int ldc,
    int M, int N, int K, int mode)
{
    __shared__ float As[BKT][BM + 1];
    __shared__ float Bs[BKT][BN + 1];
    int tid = threadIdx.x;
    int tx = tid & 15, ty = tid >> 4;
    int m0 = blockIdx.y * BM;
    int n0 = blockIdx.x * BN;
    float acc[4][4] = {};
    for (int k0 = 0; k0 < K; k0 += BKT) {
#pragma unroll
        for (int i = 0; i < 4; i++) {
            int flat = tid + 256 * i;
            int k = flat & 15, m = flat >> 4;
            int gm = m0 + m, gk = k0 + k;
            As[k][m] = (gm < M && gk < K) ? A[(size_t)gm * lda + gk] : 0.f;
        }
#pragma unroll
        for (int i = 0; i < 4; i++) {
            int flat = tid + 256 * i;
            int k = flat & 15, n = flat >> 4;
            int gn = n0 + n, gk = k0 + k;
            Bs[k][n] = (gn < N && gk < K) ? W[(size_t)gn * K + gk] : 0.f;
        }
        __syncthreads();
#pragma unroll
        for (int k = 0; k < BKT; k++) {
            float a[4], bvl[4];
#pragma unroll
            for (int i = 0; i < 4; i++) a[i] = As[k][ty + 16 * i];
#pragma unroll
            for (int j = 0; j < 4; j++) bvl[j] = Bs[k][tx + 16 * j];
#pragma unroll
            for (int i = 0; i < 4; i++)
#pragma unroll
                for (int j = 0; j < 4; j++)
                    acc[i][j] = fmaf(a[i], bvl[j], acc[i][j]);
        }
        __syncthreads();
    }
#pragma unroll
    for (int i = 0; i < 4; i++) {
        int gm = m0 + ty + 16 * i;
        if (gm >= M) continue;
#pragma unroll
        for (int j = 0; j < 4; j++) {
            int gn = n0 + tx + 16 * j;
            if (gn >= N) continue;
            float v = acc[i][j];
            if (mode >= 1) v += bias[gn];
            if (mode == 2) v = (v > 20.f) ? v : log1pf(expf(v));
            Cm[(size_t)gm * ldc + gn] = v;
        }
    }
}

// ---------------- LayerNorm over channels; writes fwd + per-batch-reversed ----
__global__ void ln_kernel(const float* __restrict__ ln_w, const float* __restrict__ ln_b) {
    int row = blockIdx.x;      // 0..4095 (b*2048 + tt)
    int c = threadIdx.x;       // 0..255
    __shared__ float red[8];
    float v = g_dg[(size_t)row * 256 + c];
    float s = v;
#pragma unroll
    for (int o = 16; o; o >>= 1) s += __shfl_xor_sync(0xffffffffu, s, o);
    if ((c & 31) == 0) red[c >> 5] = s;
    __syncthreads();
    float mean = 0.f;
#pragma unroll
    for (int i = 0; i < 8; i++) mean += red[i];
    mean *= (1.0f / 256.0f);
    __syncthreads();
    float dv = v - mean;
    float s2 = dv * dv;
#pragma unroll
    for (int o = 16; o; o >>= 1) s2 += __shfl_xor_sync(0xffffffffu, s2, o);
    if ((c & 31) == 0) red[c >> 5] = s2;
    __syncthreads();
    float var = 0.f;
#pragma unroll
    for (int i = 0; i < 8; i++) var += red[i];
    var *= (1.0f / 256.0f);
    float outv = dv * rsqrtf(var + 1e-6f) * ln_w[c] + ln_b[c];
    int b = row >> 11, tt = row & 2047;
    g_xf[0][(size_t)row * 256 + c] = outv;
    g_xf[1][(size_t)((b << 11) + (2047 - tt)) * 256 + c] = outv;
}

// ---------------- causal depthwise conv (K=4) + silu ----------------
__global__ void dwconv_kernel(const float* __restrict__ c1_w, const float* __restrict__ c1_b) {
    int idx = blockIdx.x * blockDim.x + threadIdx.x;   // 2*2*4096*512 = 8388608
    int d = idx & 511;
    int t = (idx >> 9) & 4095;
    int b = (idx >> 21) & 1;
    int dir = idx >> 22;
    const float* xz = g_xz[dir];
    const float* w = c1_w + (size_t)(dir * 512 + d) * 4;
    float acc = c1_b[dir * 512 + d];
#pragma unroll
    for (int k = 0; k < 4; k++) {
        int s = t - 3 + k;
        if (s >= 0)
            acc = fmaf(w[k], xz[(size_t)((b << 11) + (s & 2047)) * 1024 + d], acc);
    }
    float sv = acc / (1.0f + __expf(-acc));   // silu
    g_xc[dir][(size_t)(b * 4096 + t) * 512 + d] = sv;
}

// ---------------- chunked selective scan ----------------
// Pass 1: per-chunk recurrence from h=0; record h_end and prod(a).
// block = 512 threads = 32 d-channels x 16 states; grid (16 dgroups, 64 chunks, 4 dirb)
__global__ void __launch_bounds__(512) scan1_kernel(const float* __restrict__ a_log) {
    int z = blockIdx.z; int dir = z >> 1, b = z & 1;
    int chunk = blockIdx.y, dg = blockIdx.x;
    int tid = threadIdx.x;
    int dloc = tid >> 4, n = tid & 15;
    int d = dg * 32 + dloc;
    float acoef = -__expf(a_log[(size_t)(dir * 512 + d) * 16 + n]);
    const float* dtp  = g_dtb[dir] + (size_t)b * 4096 * 512;
    const float* xcp  = g_xc[dir]  + (size_t)b * 4096 * 512;
    const float* xdbp = g_xdb[dir] + (size_t)b * 4096 * 48;
    float h = 0.f, ap = 1.f;
    int t0 = chunk * CLEN;
#pragma unroll 4
    for (int tt = 0; tt < CLEN; tt++) {
        int t = t0 + tt;
        float dtv = dtp[(size_t)t * 512 + d];
        float uv  = xcp[(size_t)t * 512 + d];
        float bn  = xdbp[(size_t)t * 48 + 16 + n];
        float a = __expf(dtv * acoef);
        h = fmaf(a, h, dtv * uv * bn);
        ap *= a;
    }
    int lane = d * 16 + n;
    g_hend [z][chunk][lane] = h;
    g_aprod[z][chunk][lane] = ap;
}

// Pass 2: prefix-combine chunk states sequentially (64 steps; tiny).
// grid (16 dgroups, 4 dirb), block 512 -> one thread per (d,n) lane
__global__ void __launch_bounds__(512) scan2_kernel() {
    int z = blockIdx.y, dg = blockIdx.x;
    int tid = threadIdx.x;
    int lane = (dg * 32 + (tid >> 4)) * 16 + (tid & 15);
    float h = 0.f;
#pragma unroll 4
    for (int c = 0; c < NCHUNK; c++) {
        g_hinit[z][c][lane] = h;
        h = fmaf(g_aprod[z][c][lane], h, g_hend[z][c][lane]);
    }
}

// Pass 3: re-run chunks from true init states; emit y with D-skip and fused gate.
__global__ void __launch_bounds__(512) scan3_kernel(const float* __restrict__ a_log,
                                                    const float* __restrict__ d_p) {
    int z = blockIdx.z; int dir = z >> 1, b = z & 1;
    int chunk = blockIdx.y, dg = blockIdx.x;
    int tid = threadIdx.x;
    int dloc = tid >> 4, n = tid & 15;
    int d = dg * 32 + dloc;
    float acoef = -__expf(a_log[(size_t)(dir * 512 + d) * 16 + n]);
    float dp = d_p[dir * 512 + d];
    const float* dtp  = g_dtb[dir] + (size_t)b * 4096 * 512;
    const float* xcp  = g_xc[dir]  + (size_t)b * 4096 * 512;
    const float* xdbp = g_xdb[dir] + (size_t)b * 4096 * 48;
    const float* xzp  = g_xz[dir];
    float* yp = g_y[dir] + (size_t)b * 4096 * 512;
    float h = g_hinit[z][chunk][d * 16 + n];
    int t0 = chunk * CLEN;
    for (int tt = 0; tt < CLEN; tt++) {
        int t = t0 + tt;
        float dtv = dtp[(size_t)t * 512 + d];
        float uv  = xcp[(size_t)t * 512 + d];
        float bn  = xdbp[(size_t)t * 48 + 16 + n];
        float cn  = xdbp[(size_t)t * 48 + 32 + n];
        float a = __expf(dtv * acoef);
        h = fmaf(a, h, dtv * uv * bn);
        float p = h * cn;
        p += __shfl_xor_sync(0xffffffffu, p, 1);
        p += __shfl_xor_sync(0xffffffffu, p, 2);
        p += __shfl_xor_sync(0xffffffffu, p, 4);
        p += __shfl_xor_sync(0xffffffffu, p, 8);
        if (n == 0) {
            float yv = fmaf(uv, dp, p);
            float zv = xzp[(size_t)((b << 11) + (t & 2047)) * 1024 + 512 + d];
            yv *= zv / (1.0f + __expf(-zv));    // fused gate: y *= silu(z)
            yp[(size_t)t * 512 + d] = yv;
        }
    }
}

// ---------------- combine fwd/bwd + scatter into spatial grids ----------------
__device__ __forceinline__ float comb_val(int b, int t, int c) {
    return 0.5f * (g_yp[0][(size_t)(b * 4096 + t) * 256 + c] +
                   g_yp[1][(size_t)(b * 4096 + 4095 - t) * 256 + c]);
}
__global__ void scatter0_kernel() {
    int idx = blockIdx.x * blockDim.x + threadIdx.x;   // 2*256*32*32 = 524288
    int w = idx & 31;
    int h = (idx >> 5) & 31;
    int c = (idx >> 10) & 255;
    int b = idx >> 18;
    int t1 = h * 32 + w;               // hw chunk (chunk 0)
    int t2 = 2048 + w * 32 + h;        // wh chunk (chunk 2), transposed scatter
    g_grid0[idx] = comb_val(b, t1, c) + comb_val(b, t2, c);
}
__global__ void scatter1_kernel() {
    int idx = blockIdx.x * blockDim.x + threadIdx.x;   // 2*256*64*16 = 524288
    int w = idx & 15;
    int h = (idx >> 4) & 63;
    int c = (idx >> 10) & 255;
    int b = idx >> 18;
    int t1 = 1024 + h * 16 + w;        // hw chunk (chunk 1)
    int t2 = 3072 + w * 64 + h;        // wh chunk (chunk 3)
    g_grid1[idx] = comb_val(b, t1, c) + comb_val(b, t2, c);
}

// ---------------- x4 bilinear upsample (jax half-pixel; clamp edges) ----------
__device__ __forceinline__ void up_coords(int o, int nmax, int& i0, int& i1, float& f) {
    const float F[4] = {0.625f, 0.875f, 0.125f, 0.375f};
    int r = o & 3, p = o >> 2;
    f = F[r];
    i0 = p - (r < 2 ? 1 : 0);
    i1 = i0 + 1;
    if (i0 < 0) i0 = 0;
    if (i1 > nmax) i1 = nmax;
}
__global__ void up0_kernel(float* __restrict__ out) {
    int idx = blockIdx.x * blockDim.x + threadIdx.x;   // 2*256*128*128 = 8388608
    int j = idx & 127;
    int i = (idx >> 7) & 127;
    int c = (idx >> 14) & 255;
    int b = idx >> 22;
    int i0, i1, j0, j1; float fi, fj;
    up_coords(i, 31, i0, i1, fi);
    up_coords(j, 31, j0, j1, fj);
    const float* g = g_grid0 + (size_t)(b * 256 + c) * 1024;
    float v00 = g[i0 * 32 + j0], v01 = g[i0 * 32 + j1];
    float v10 = g[i1 * 32 + j0], v11 = g[i1 * 32 + j1];
    out[idx] = (1.f - fi) * ((1.f - fj) * v00 + fj * v01) + fi * ((1.f - fj) * v10 + fj * v11);
}
__global__ void up1_kernel(float* __restrict__ out) {
    int idx = blockIdx.x * blockDim.x + threadIdx.x;   // 2*256*256*64 = 8388608
    int j = idx & 63;
    int i = (idx >> 6) & 255;
    int c = (idx >> 14) & 255;
    int b = idx >> 22;
    int i0, i1, j0, j1; float fi, fj;
    up_coords(i, 63, i0, i1, fi);
    up_coords(j, 15, j0, j1, fj);
    const float* g = g_grid1 + (size_t)(b * 256 + c) * 1024;
    float v00 = g[i0 * 16 + j0], v01 = g[i0 * 16 + j1];
    float v10 = g[i1 * 16 + j0], v11 = g[i1 * 16 + j1];
    out[idx] = (1.f - fi) * ((1.f - fj) * v00 + fj * v01) + fi * ((1.f - fj) * v10 + fj * v11);
}

// ---------------- host launch ----------------
extern "C" void kernel_launch(void* const* d_in, const int* in_sizes, int n_in,
                              void* d_out, int out_size) {
    const float* x0     = (const float*)d_in[0];
    const float* x1     = (const float*)d_in[1];
    const float* conv_w = (const float*)d_in[2];
    const float* conv_b = (const float*)d_in[3];
    const float* ln_w   = (const float*)d_in[4];
    const float* ln_b   = (const float*)d_in[5];
    const float* in_w   = (const float*)d_in[6];
    const float* c1_w   = (const float*)d_in[7];
    const float* c1_b   = (const float*)d_in[8];
    const float* xp_w   = (const float*)d_in[9];
    const float* dt_w   = (const float*)d_in[10];
    const float* dt_b   = (const float*)d_in[11];
    const float* a_log  = (const float*)d_in[12];
    const float* d_p    = (const float*)d_in[13];
    const float* out_w  = (const float*)d_in[14];
    float* out = (float*)d_out;

    float *patches, *dgp, *xf, *xz, *xc, *xdb, *dtb, *yb, *ypb;
    cudaGetSymbolAddress((void**)&patches, g_patches);
    cudaGetSymbolAddress((void**)&dgp, g_dgp);
    cudaGetSymbolAddress((void**)&xf, g_xf);
    cudaGetSymbolAddress((void**)&xz, g_xz);
    cudaGetSymbolAddress((void**)&xc, g_xc);
    cudaGetSymbolAddress((void**)&xdb, g_xdb);
    cudaGetSymbolAddress((void**)&dtb, g_dtb);
    cudaGetSymbolAddress((void**)&yb, g_y);
    cudaGetSymbolAddress((void**)&ypb, g_yp);

    // 1) im2col + down-conv GEMM (split-K x4 for occupancy) + reduce(+bias)
    im2col_kernel<<<4096, 256>>>(x0, x1);
    gemm128_kernel<<<dim3(2, 32, 4), 256>>>(patches, 4096, conv_w, nullptr,
                                            dgp, 256, 4096, 256, 4096, 0);
    reduce_dg_kernel<<<4096, 256>>>(conv_b);

    // 2) LayerNorm -> base tokens fwd/rev
    ln_kernel<<<4096, 256>>>(ln_w, ln_b);

    // 3) in-proj per direction (half-length: sequence repeats the base tokens)
    for (int dir = 0; dir < 2; dir++) {
        gemm128_kernel<<<dim3(8, 32), 256>>>(
            xf + (size_t)dir * 4096 * 256, 256,
            in_w + (size_t)dir * 1024 * 256, nullptr,
            xz + (size_t)dir * 4096 * 1024, 1024, 4096, 1024, 256, 0);
    }

    // 4) causal dwconv + silu (full length, both dirs)
    dwconv_kernel<<<32768, 256>>>(c1_w, c1_b);

    // 5) xp projection (ragged N=48 -> 64x64 kernel) and dt (softplus + bias)
    for (int dir = 0; dir < 2; dir++) {
        gemm_kernel<<<dim3(1, 128), 256>>>(
            xc + (size_t)dir * 8192 * 512, 512,
            xp_w + (size_t)dir * 48 * 512, nullptr,
            xdb + (size_t)dir * 8192 * 48, 48, 8192, 48, 512, 0);
        gemm128_kernel<<<dim3(4, 64), 256>>>(
            xdb + (size_t)dir * 8192 * 48, 48,
            dt_w + (size_t)dir * 512 * 16, dt_b + (size_t)dir * 512,
            dtb + (size_t)dir * 8192 * 512, 512, 8192, 512, 16, 2);
    }

    // 6) chunked parallel selective scan (gate fused into pass 3)
    scan1_kernel<<<dim3(16, NCHUNK, 4), 512>>>(a_log);
    scan2_kernel<<<dim3(16, 4), 512>>>();
    scan3_kernel<<<dim3(16, NCHUNK, 4), 512>>>(a_log, d_p);

    // 7) out-proj
    for (int dir = 0; dir < 2; dir++) {
        gemm128_kernel<<<dim3(2, 64), 256>>>(
            yb + (size_t)dir * 8192 * 512, 512,
            out_w + (size_t)dir * 256 * 512, nullptr,
            ypb + (size_t)dir * 8192 * 256, 256, 8192, 256, 512, 0);
    }

    // 8) combine directions + scatter to grids, then bilinear x4 upsample
    scatter0_kernel<<<2048, 256>>>();
    scatter1_kernel<<<2048, 256>>>();
    up0_kernel<<<32768, 256>>>(out);
    up1_kernel<<<32768, 256>>>(out + 8388608);
}